// round 15
// baseline (speedup 1.0000x reference)
#include <cuda_runtime.h>

// ALIF forward: x_seq [T, n_flat] -> spikes [T, n_flat]. HBM-bound streaming
// recurrence (536 MB traffic, zero reuse). R15 = R14 (float2, interleaved
// one-LDG-per-step prefetch, full-group store batch, 1024 CTAs x 32) with
// prefetch depth 2 -> 3 (rotation A,B,C at U=16): each group's loads get
// ~2 stages (~800-1200 cyc) of lead time, covering NAT-clock DRAM latency
// at group boundaries. regs ~210-225 (< 255; spill is the abort criterion).

static constexpr int T_STEPS = 1024;
static constexpr int U = 16;         // time steps per group = store batch

__global__ __launch_bounds__(32)
void ALIF_24309514895931_kernel(
    const float2* __restrict__ x,     // [T, n2]
    const float2* __restrict__ v0,    // [n2]
    const float2* __restrict__ a0,    // [n2]
    const float* __restrict__ p_decay_v,
    const float* __restrict__ p_decay_a,
    const float* __restrict__ p_threshold,
    const float* __restrict__ p_beta,
    float2* __restrict__ out,         // [T, n2]
    int n2)                           // n_flat / 2
{
    const int i = blockIdx.x * blockDim.x + threadIdx.x;
    if (i >= n2) return;

    const float dv   = *p_decay_v;
    const float da   = *p_decay_a;
    const float thr  = *p_threshold;
    const float beta = *p_beta;

    float2 v = v0[i];
    float2 a = a0[i];

    const float2* xp = x + i;
    float2*       op = out + i;
    const int stride = n2;            // max index T*n2 = 33.5M -> 32-bit safe

    float2 bufA[U], bufB[U], bufC[U];

    // Prologue: A <- group 0, B <- group 1, C <- group 2.
    #pragma unroll
    for (int u = 0; u < U; u++) bufA[u] = xp[u * stride];
    #pragma unroll
    for (int u = 0; u < U; u++) bufB[u] = xp[(U + u) * stride];
    #pragma unroll
    for (int u = 0; u < U; u++) bufC[u] = xp[(2 * U + u) * stride];

    // Consume CUR (group tcur): interleave one prefetch LDG per step for
    // group tcur+3U (guarded); stage all U spikes in sreg, then burst-store.
#define ALIF_STAGE(tcur, CUR)                                               \
    {                                                                       \
        const int obase = (tcur) * stride;                                  \
        const int pf    = (tcur) + 3 * U;                                   \
        const bool dopf = (pf < T_STEPS);                                   \
        const int pbase = pf * stride;                                      \
        float2 sreg[U];                                                     \
        _Pragma("unroll")                                                   \
        for (int u = 0; u < U; u++) {                                       \
            float2 xv = CUR[u];                                             \
            if (dopf)                                                       \
                CUR[u] = xp[pbase + u * stride];                            \
            float2 s;                                                       \
            v.x = fmaf(dv, v.x, xv.x);                                      \
            v.y = fmaf(dv, v.y, xv.y);                                      \
            float thx = fmaf(beta, a.x, thr);                               \
            float thy = fmaf(beta, a.y, thr);                               \
            s.x = (v.x > thx) ? 1.0f : 0.0f;                                \
            s.y = (v.y > thy) ? 1.0f : 0.0f;                                \
            v.x = fmaf(-s.x, thx, v.x);                                     \
            v.y = fmaf(-s.y, thy, v.y);                                     \
            a.x = fmaf(da, a.x, s.x);                                       \
            a.y = fmaf(da, a.y, s.y);                                       \
            sreg[u] = s;                                                    \
        }                                                                   \
        _Pragma("unroll")                                                   \
        for (int u = 0; u < U; u++)                                         \
            op[obase + u * stride] = sreg[u];                               \
    }

    // 64 groups of U=16. Main loop: 21 iterations x 3 stages = groups 0..62
    // (prefetch of groups 3..63; 64/65 skipped by guard). Tail: group 63
    // (63 mod 3 == 0 -> bufA), consume-only.
    #pragma unroll 1
    for (int t = 0; t < T_STEPS - 3 * U; t += 3 * U) {
        ALIF_STAGE(t,         bufA);   // consume A(g),   A <- g+3
        ALIF_STAGE(t + U,     bufB);   // consume B(g+1), B <- g+4
        ALIF_STAGE(t + 2 * U, bufC);   // consume C(g+2), C <- g+5
    }
    ALIF_STAGE(T_STEPS - U, bufA);     // group 63, prefetch guard off
#undef ALIF_STAGE
}

extern "C" void kernel_launch(void* const* d_in, const int* in_sizes, int n_in,
                              void* d_out, int out_size) {
    const float* x     = (const float*)d_in[0];
    const float* v0    = (const float*)d_in[1];
    const float* a0    = (const float*)d_in[2];
    const float* dv    = (const float*)d_in[3];
    const float* da    = (const float*)d_in[4];
    const float* thr   = (const float*)d_in[5];
    const float* beta  = (const float*)d_in[6];
    // d_in[7] = alpha: unused in forward pass.

    const int n_flat = in_sizes[1];
    const int n2 = n_flat / 2;        // n_flat = 65536, even

    dim3 block(32);
    dim3 grid((n2 + 31) / 32);
    ALIF_24309514895931_kernel<<<grid, block>>>(
        (const float2*)x, (const float2*)v0, (const float2*)a0,
        dv, da, thr, beta, (float2*)d_out, n2);
}

// round 16
// speedup vs baseline: 1.1692x; 1.1692x over previous
#include <cuda_runtime.h>

// ALIF forward: x_seq [T, n_flat] -> spikes [T, n_flat]. HBM-bound streaming
// recurrence (536 MB traffic, zero reuse). FINAL (= R14, empirical optimum):
//  - float2: 2 neuron columns/thread, 2 independent recurrence chains.
//  - Ping-pong depth-2 prefetch, U=16: interleaved one-LDG-per-step prefetch
//    of group t+2U while consuming group t (sustained ~4 MB in flight).
//    Depth-3 variants regressed twice (L1tex queue-position latency grows
//    with outstanding-load depth at 7 warps/SM); depth-2 is the optimum.
//  - Full-group store batch: 16 spikes staged in regs, then 16 back-to-back
//    STG.64 -> long DRAM write runs, fewer R/W bus turnarounds.
//  - 32768 threads, block=32 -> 1024 CTAs -> 6.92 CTAs/SM balance (max 7).
//  - regs ~160: no spill. Measured: 6.9 TB/s wall (~86% spec HBM).

static constexpr int T_STEPS = 1024;
static constexpr int U = 16;         // time steps per group = store batch

__global__ __launch_bounds__(32)
void ALIF_24309514895931_kernel(
    const float2* __restrict__ x,     // [T, n2]
    const float2* __restrict__ v0,    // [n2]
    const float2* __restrict__ a0,    // [n2]
    const float* __restrict__ p_decay_v,
    const float* __restrict__ p_decay_a,
    const float* __restrict__ p_threshold,
    const float* __restrict__ p_beta,
    float2* __restrict__ out,         // [T, n2]
    int n2)                           // n_flat / 2
{
    const int i = blockIdx.x * blockDim.x + threadIdx.x;
    if (i >= n2) return;

    const float dv   = *p_decay_v;
    const float da   = *p_decay_a;
    const float thr  = *p_threshold;
    const float beta = *p_beta;

    float2 v = v0[i];
    float2 a = a0[i];

    const float2* xp = x + i;
    float2*       op = out + i;
    const int stride = n2;            // max index T*n2 = 33.5M -> 32-bit safe

    float2 bufA[U], bufB[U];

    // Prologue: A <- group 0, B <- group 1.
    #pragma unroll
    for (int u = 0; u < U; u++) bufA[u] = xp[u * stride];
    #pragma unroll
    for (int u = 0; u < U; u++) bufB[u] = xp[(U + u) * stride];

    // Consume CUR (group tcur): loads (prefetch of group tcur+2U) interleave
    // one-per-step; all U spikes staged in sreg[], then one burst of U
    // back-to-back STG.64.
#define ALIF_STAGE(tcur, CUR, DO_PREFETCH)                                  \
    {                                                                       \
        const int obase = (tcur) * stride;                                  \
        const int pbase = ((tcur) + 2 * U) * stride;                        \
        float2 sreg[U];                                                     \
        _Pragma("unroll")                                                   \
        for (int u = 0; u < U; u++) {                                       \
            float2 xv = CUR[u];                                             \
            if (DO_PREFETCH)                                                \
                CUR[u] = xp[pbase + u * stride];                            \
            float2 s;                                                       \
            v.x = fmaf(dv, v.x, xv.x);                                      \
            v.y = fmaf(dv, v.y, xv.y);                                      \
            float thx = fmaf(beta, a.x, thr);                               \
            float thy = fmaf(beta, a.y, thr);                               \
            s.x = (v.x > thx) ? 1.0f : 0.0f;                                \
            s.y = (v.y > thy) ? 1.0f : 0.0f;                                \
            v.x = fmaf(-s.x, thx, v.x);                                     \
            v.y = fmaf(-s.y, thy, v.y);                                     \
            a.x = fmaf(da, a.x, s.x);                                       \
            a.y = fmaf(da, a.y, s.y);                                       \
            sreg[u] = s;                                                    \
        }                                                                   \
        _Pragma("unroll")                                                   \
        for (int u = 0; u < U; u++)                                         \
            op[obase + u * stride] = sreg[u];                               \
    }

    // 64 groups of U=16: groups 0..61 with prefetch, last two consume-only.
    #pragma unroll 1
    for (int t = 0; t < T_STEPS - 2 * U; t += 2 * U) {
        ALIF_STAGE(t,     bufA, true);    // consume A(t),   A <- t+2U
        ALIF_STAGE(t + U, bufB, true);    // consume B(t+U), B <- t+3U
    }
    ALIF_STAGE(T_STEPS - 2 * U, bufA, false);
    ALIF_STAGE(T_STEPS - U,     bufB, false);
#undef ALIF_STAGE
}

extern "C" void kernel_launch(void* const* d_in, const int* in_sizes, int n_in,
                              void* d_out, int out_size) {
    const float* x     = (const float*)d_in[0];
    const float* v0    = (const float*)d_in[1];
    const float* a0    = (const float*)d_in[2];
    const float* dv    = (const float*)d_in[3];
    const float* da    = (const float*)d_in[4];
    const float* thr   = (const float*)d_in[5];
    const float* beta  = (const float*)d_in[6];
    // d_in[7] = alpha: unused in forward pass.

    const int n_flat = in_sizes[1];
    const int n2 = n_flat / 2;        // n_flat = 65536, even

    dim3 block(32);
    dim3 grid((n2 + 31) / 32);
    ALIF_24309514895931_kernel<<<grid, block>>>(
        (const float2*)x, (const float2*)v0, (const float2*)a0,
        dv, da, thr, beta, (float2*)d_out, n2);
}